// round 11
// baseline (speedup 1.0000x reference)
#include <cuda_runtime.h>
#include <cuda_bf16.h>
#include <cstdint>

// Problem constants
#define D_MODEL 768
#define SEQ     4096
#define NH      12
#define DKH     64
#define DD      (D_MODEL * D_MODEL)
#define SD      (SEQ * D_MODEL)

// ---------------------------------------------------------------------------
// Scratch (no allocations allowed -> device globals)
// ---------------------------------------------------------------------------
__device__ __align__(128) __nv_bfloat16 g_Wsh[4 * DD];   // Wq,Wk,Wv,Wo transposed+split hi
__device__ __align__(128) __nv_bfloat16 g_Wsl[4 * DD];   // lo
__device__ __align__(128) __nv_bfloat16 g_Xh[3 * SD];    // q,k,v input splits; later ctx (slot 0)
__device__ __align__(128) __nv_bfloat16 g_Xl[3 * SD];
__device__ __align__(128) __nv_bfloat16 g_Ph[3 * SD];    // projected Q,K,V hi
__device__ __align__(128) __nv_bfloat16 g_Pl[3 * SD];    // lo

// ---------------------------------------------------------------------------
// PTX helpers (plain-sm_103-legal: mma.sync, ldmatrix, cp.async)
// ---------------------------------------------------------------------------
__device__ __forceinline__ uint32_t smem_to_u32(const void* p) {
    uint32_t a;
    asm("{ .reg .u64 t; cvta.to.shared.u64 t, %1; cvt.u32.u64 %0, t; }" : "=r"(a) : "l"(p));
    return a;
}
__device__ __forceinline__ void cp16(uint32_t dst, const void* src) {
    asm volatile("cp.async.cg.shared.global [%0], [%1], 16;" :: "r"(dst), "l"(src) : "memory");
}
#define CP_COMMIT() asm volatile("cp.async.commit_group;" ::: "memory")
#define CP_WAIT(n)  asm volatile("cp.async.wait_group %0;" :: "n"(n) : "memory")

__device__ __forceinline__ void ldsm4(uint32_t* r, uint32_t addr) {
    asm volatile("ldmatrix.sync.aligned.m8n8.x4.shared.b16 {%0,%1,%2,%3}, [%4];"
                 : "=r"(r[0]), "=r"(r[1]), "=r"(r[2]), "=r"(r[3]) : "r"(addr));
}
__device__ __forceinline__ void ldsm4t(uint32_t* r, uint32_t addr) {
    asm volatile("ldmatrix.sync.aligned.m8n8.x4.trans.shared.b16 {%0,%1,%2,%3}, [%4];"
                 : "=r"(r[0]), "=r"(r[1]), "=r"(r[2]), "=r"(r[3]) : "r"(addr));
}
__device__ __forceinline__ void mma16816(float* d, const uint32_t* a, const uint32_t* b) {
    asm volatile("mma.sync.aligned.m16n8k16.row.col.f32.bf16.bf16.f32 "
                 "{%0,%1,%2,%3}, {%4,%5,%6,%7}, {%8,%9}, {%0,%1,%2,%3};"
                 : "+f"(d[0]), "+f"(d[1]), "+f"(d[2]), "+f"(d[3])
                 : "r"(a[0]), "r"(a[1]), "r"(a[2]), "r"(a[3]), "r"(b[0]), "r"(b[1]));
}
__device__ __forceinline__ uint32_t sw128(uint32_t off) { return off ^ ((off >> 3) & 0x70); }
__device__ __forceinline__ uint32_t pack2(float a, float b) {
    __nv_bfloat162 t = __floats2bfloat162_rn(a, b);
    return *(uint32_t*)&t;
}

// ---------------------------------------------------------------------------
// Fused conversion kernels
// ---------------------------------------------------------------------------
__global__ void split_all(const float* __restrict__ q, const float* __restrict__ k,
                          const float* __restrict__ v,
                          __nv_bfloat16* __restrict__ Hi, __nv_bfloat16* __restrict__ Lo) {
    const int z = blockIdx.y;
    const float* A = (z == 0) ? q : (z == 1) ? k : v;
    __nv_bfloat16* hi = Hi + (size_t)z * SD;
    __nv_bfloat16* lo = Lo + (size_t)z * SD;
    const int i = (blockIdx.x * 256 + threadIdx.x) * 4;
    float4 a = *(const float4*)(A + i);
    float vv[4] = {a.x, a.y, a.z, a.w};
#pragma unroll
    for (int j = 0; j < 4; j++) {
        __nv_bfloat16 h = __float2bfloat16(vv[j]);
        hi[i + j] = h;
        lo[i + j] = __float2bfloat16(vv[j] - __bfloat162float(h));
    }
}

// All four W[K,N] row-major -> Wt[N,K] K-major, split into hi/lo
__global__ void transpose_all(const float* __restrict__ W0, const float* __restrict__ W1,
                              const float* __restrict__ W2, const float* __restrict__ W3,
                              __nv_bfloat16* __restrict__ Th, __nv_bfloat16* __restrict__ Tl) {
    const int z = blockIdx.z;
    const float* W = (z == 0) ? W0 : (z == 1) ? W1 : (z == 2) ? W2 : W3;
    __nv_bfloat16* th = Th + (size_t)z * DD;
    __nv_bfloat16* tl = Tl + (size_t)z * DD;
    __shared__ float t[32][33];
    const int bx = blockIdx.x * 32;
    const int by = blockIdx.y * 32;
    const int x = threadIdx.x, y = threadIdx.y;
#pragma unroll
    for (int i = 0; i < 32; i += 8)
        t[y + i][x] = W[(by + y + i) * D_MODEL + bx + x];
    __syncthreads();
#pragma unroll
    for (int i = 0; i < 32; i += 8) {
        const float v = t[x][y + i];
        __nv_bfloat16 h = __float2bfloat16(v);
        const int o = (bx + y + i) * D_MODEL + by + x;
        th[o] = h;
        tl[o] = __float2bfloat16(v - __bfloat162float(h));
    }
}

// ---------------------------------------------------------------------------
// HMMA GEMM (batched over blockIdx.z):
// C_z = (Ah+Al)_z [M,K] @ (Bh+Bl)_z [N,K]^T + bias_z, scale for z==0.
// SPLIT: bf16 hi/lo split output; else fp32.
// ---------------------------------------------------------------------------
#define TC_BM 128
#define TC_BN 128
#define TC_BK 64
#define TC_NKCH (D_MODEL / TC_BK)
#define TC_ITEMS (3 * TC_NKCH)
#define TC_STAGE 32768
#define TC_SMEM  (2 * TC_STAGE)

template <bool SPLIT>
__global__ __launch_bounds__(256)
void gemm_tc(const __nv_bfloat16* __restrict__ Ahb, const __nv_bfloat16* __restrict__ Alb,
             const __nv_bfloat16* __restrict__ Bhb, const __nv_bfloat16* __restrict__ Blb,
             const float* __restrict__ b0, const float* __restrict__ b1,
             const float* __restrict__ b2,
             float* __restrict__ Cf,
             __nv_bfloat16* __restrict__ Chb, __nv_bfloat16* __restrict__ Clb, float scale0) {
    extern __shared__ char smem[];
    const uint32_t sb = smem_to_u32(smem);
    const int tid  = threadIdx.x;
    const int wid  = tid >> 5;
    const int lane = tid & 31;
    const int z    = blockIdx.z;
    const int row0 = blockIdx.y * TC_BM;
    const int col0 = blockIdx.x * TC_BN;
    const int wm = (wid & 3) * 32;
    const int wn = (wid >> 2) * 64;

    const __nv_bfloat16* Ah = Ahb + (size_t)z * SD;
    const __nv_bfloat16* Al = Alb + (size_t)z * SD;
    const __nv_bfloat16* Bh = Bhb + (size_t)z * DD;
    const __nv_bfloat16* Bl = Blb + (size_t)z * DD;
    const float* bias = (z == 0) ? b0 : (z == 1) ? b1 : b2;
    const float scale = (z == 0) ? scale0 : 1.0f;

    float d[2][8][4];
#pragma unroll
    for (int mt = 0; mt < 2; mt++)
#pragma unroll
        for (int nt = 0; nt < 8; nt++)
#pragma unroll
            for (int e = 0; e < 4; e++) d[mt][nt][e] = 0.f;

    auto load_item = [&](int item, int stage) {
        const int pass = item / TC_NKCH;
        const int k0 = (item % TC_NKCH) * TC_BK;
        const __nv_bfloat16* Asrc = (pass == 2) ? Al : Ah;
        const __nv_bfloat16* Bsrc = (pass == 1) ? Bl : Bh;
        const uint32_t base = sb + (uint32_t)stage * TC_STAGE;
#pragma unroll
        for (int i = 0; i < 4; i++) {
            const int v = tid + i * 256;
            const int r = v >> 3;
            const int c = v & 7;
            const uint32_t sw = sw128((uint32_t)(r * 128 + c * 16));
            cp16(base + sw,         Asrc + (size_t)(row0 + r) * D_MODEL + k0 + c * 8);
            cp16(base + 16384 + sw, Bsrc + (size_t)(col0 + r) * D_MODEL + k0 + c * 8);
        }
    };

    load_item(0, 0);
    CP_COMMIT();

    for (int item = 0; item < TC_ITEMS; item++) {
        const int s = item & 1;
        if (item + 1 < TC_ITEMS) {
            load_item(item + 1, s ^ 1);
            CP_COMMIT();
            CP_WAIT(1);
        } else {
            CP_WAIT(0);
        }
        __syncthreads();

        const uint32_t abase = sb + (uint32_t)s * TC_STAGE;
        const uint32_t bbase = abase + 16384;

#pragma unroll
        for (int ks = 0; ks < 4; ks++) {
            uint32_t a[2][4];
#pragma unroll
            for (int mt = 0; mt < 2; mt++) {
                const int r = wm + mt * 16 + (lane & 15);
                const int cb = ks * 32 + ((lane >> 4) << 4);
                ldsm4(a[mt], abase + sw128((uint32_t)(r * 128 + cb)));
            }
#pragma unroll
            for (int t = 0; t < 4; t++) {
                const int nr = wn + t * 16 + ((lane >> 4) << 3) + (lane & 7);
                const int cb = ks * 32 + ((lane >> 3) & 1) * 16;
                uint32_t bb[4];
                ldsm4(bb, bbase + sw128((uint32_t)(nr * 128 + cb)));
#pragma unroll
                for (int mt = 0; mt < 2; mt++) {
                    mma16816(d[mt][t * 2],     a[mt], &bb[0]);
                    mma16816(d[mt][t * 2 + 1], a[mt], &bb[2]);
                }
            }
        }
        __syncthreads();
    }

#pragma unroll
    for (int mt = 0; mt < 2; mt++) {
        const int rA = row0 + wm + mt * 16 + (lane >> 2);
        const int rB = rA + 8;
#pragma unroll
        for (int nt = 0; nt < 8; nt++) {
            const int c = col0 + wn + nt * 8 + (lane & 3) * 2;
            const float bb0 = bias[c], bb1 = bias[c + 1];
            float v0 = (d[mt][nt][0] + bb0) * scale;
            float v1 = (d[mt][nt][1] + bb1) * scale;
            float v2 = (d[mt][nt][2] + bb0) * scale;
            float v3 = (d[mt][nt][3] + bb1) * scale;
            if (!SPLIT) {
                *(float2*)(Cf + (size_t)rA * D_MODEL + c) = make_float2(v0, v1);
                *(float2*)(Cf + (size_t)rB * D_MODEL + c) = make_float2(v2, v3);
            } else {
                __nv_bfloat16* Ch = Chb + (size_t)z * SD;
                __nv_bfloat16* Cl = Clb + (size_t)z * SD;
                __nv_bfloat162 hA = __floats2bfloat162_rn(v0, v1);
                __nv_bfloat162 lA = __floats2bfloat162_rn(v0 - __bfloat162float(hA.x),
                                                          v1 - __bfloat162float(hA.y));
                __nv_bfloat162 hB = __floats2bfloat162_rn(v2, v3);
                __nv_bfloat162 lB = __floats2bfloat162_rn(v2 - __bfloat162float(hB.x),
                                                          v3 - __bfloat162float(hB.y));
                *(__nv_bfloat162*)(Ch + (size_t)rA * D_MODEL + c) = hA;
                *(__nv_bfloat162*)(Cl + (size_t)rA * D_MODEL + c) = lA;
                *(__nv_bfloat162*)(Ch + (size_t)rB * D_MODEL + c) = hB;
                *(__nv_bfloat162*)(Cl + (size_t)rB * D_MODEL + c) = lB;
            }
        }
    }
}

// ---------------------------------------------------------------------------
// HMMA flash attention. CTA = 128 queries x 1 head. 8 warps x m16 rows.
// BN=64 keys/iter, K/V (hi+lo) double-buffered via cp.async.
// S = Qh Kh + Qh Kl + Ql Kh; ctx = Ph Vh + Ph Vl + Pl Vh.
// MMA issue order: tile-pairs -> 4 independent accumulators between
// dependent reuses (distance 4 = ~16 issue cycles).
// ---------------------------------------------------------------------------
#define FB_M 128
#define FB_N 64
#define F_NITER (SEQ / FB_N)          /* 64 */
#define SQH 0
#define SQL 16384
#define SKV 32768                     /* per-stage: Kh 0 | Kl 8K | Vh 16K | Vl 24K */
#define F_STAGE 32768
#define FA2_SMEM (SKV + 2 * F_STAGE)  /* 98304 */

__global__ __launch_bounds__(256)
void flash_tc(const __nv_bfloat16* __restrict__ Qhg, const __nv_bfloat16* __restrict__ Qlg,
              const __nv_bfloat16* __restrict__ Khg, const __nv_bfloat16* __restrict__ Klg,
              const __nv_bfloat16* __restrict__ Vhg, const __nv_bfloat16* __restrict__ Vlg,
              __nv_bfloat16* __restrict__ Ch, __nv_bfloat16* __restrict__ Cl) {
    extern __shared__ char smem[];
    const uint32_t sb = smem_to_u32(smem);
    const int tid  = threadIdx.x;
    const int wid  = tid >> 5;
    const int lane = tid & 31;
    const int q0 = blockIdx.x * FB_M;
    const int hc = blockIdx.y * DKH;
    const int wr = wid * 16;

    // ---- prologue: Q (hi+lo) + KV stage 0 ----
#pragma unroll
    for (int i = 0; i < 4; i++) {
        const int v = tid + i * 256;
        const int r = v >> 3, c = v & 7;
        const uint32_t sw = sw128((uint32_t)(r * 128 + c * 16));
        cp16(sb + SQH + sw, Qhg + (size_t)(q0 + r) * D_MODEL + hc + c * 8);
        cp16(sb + SQL + sw, Qlg + (size_t)(q0 + r) * D_MODEL + hc + c * 8);
    }
    CP_COMMIT();

    const __nv_bfloat16* kvsrc[4] = {Khg, Klg, Vhg, Vlg};
    auto load_kv = [&](int it, int st) {
        const int kb0 = it * FB_N;
        const uint32_t base = sb + SKV + (uint32_t)st * F_STAGE;
#pragma unroll
        for (int i = 0; i < 8; i++) {
            const int mat = i >> 1;
            const int v = (tid + i * 256) & 511;
            const int r = v >> 3, c = v & 7;
            cp16(base + (uint32_t)mat * 8192u + sw128((uint32_t)(r * 128 + c * 16)),
                 kvsrc[mat] + (size_t)(kb0 + r) * D_MODEL + hc + c * 8);
        }
    };
    load_kv(0, 0);
    CP_COMMIT();
    CP_WAIT(0);
    __syncthreads();

    // ---- resident Q fragments ----
    uint32_t qh[4][4], ql[4][4];
#pragma unroll
    for (int ks = 0; ks < 4; ks++) {
        const int r = wr + (lane & 15);
        const int cb = ks * 32 + ((lane >> 4) << 4);
        const uint32_t off = sw128((uint32_t)(r * 128 + cb));
        ldsm4(qh[ks], sb + SQH + off);
        ldsm4(ql[ks], sb + SQL + off);
    }

    float m0 = -1e30f, m1 = -1e30f, sum0 = 0.f, sum1 = 0.f;
    float O[8][4];
#pragma unroll
    for (int nt = 0; nt < 8; nt++)
#pragma unroll
        for (int e = 0; e < 4; e++) O[nt][e] = 0.f;

#pragma unroll 1
    for (int it = 0; it < F_NITER; it++) {
        const int s = it & 1;
        if (it + 1 < F_NITER) {
            load_kv(it + 1, s ^ 1);
            CP_COMMIT();
            CP_WAIT(1);
        } else {
            CP_WAIT(0);
        }
        __syncthreads();

        const uint32_t kbh = sb + SKV + (uint32_t)s * F_STAGE;
        const uint32_t kbl = kbh + 8192;
        const uint32_t vbh = kbh + 16384;
        const uint32_t vbl = kbh + 24576;

        // ---- S = Q K^T (3-pass split), tile-pair interleaved ----
        float S[8][4];
#pragma unroll
        for (int nt = 0; nt < 8; nt++)
#pragma unroll
            for (int e = 0; e < 4; e++) S[nt][e] = 0.f;

#pragma unroll
        for (int ks = 0; ks < 4; ks++) {
            const int cb = ks * 32 + ((lane >> 3) & 1) * 16;
#pragma unroll
            for (int tp = 0; tp < 2; tp++) {
                const int nr0 = (2 * tp) * 16 + ((lane >> 4) << 3) + (lane & 7);
                const uint32_t o0 = sw128((uint32_t)(nr0 * 128 + cb));
                const uint32_t o1 = sw128((uint32_t)((nr0 + 16) * 128 + cb));
                uint32_t kh0[4], kh1[4], kl0[4], kl1[4];
                ldsm4(kh0, kbh + o0);
                ldsm4(kh1, kbh + o1);
                ldsm4(kl0, kbl + o0);
                ldsm4(kl1, kbl + o1);
                float* S0 = S[4 * tp];     float* S1 = S[4 * tp + 1];
                float* S2 = S[4 * tp + 2]; float* S3 = S[4 * tp + 3];
                mma16816(S0, qh[ks], &kh0[0]); mma16816(S1, qh[ks], &kh0[2]);
                mma16816(S2, qh[ks], &kh1[0]); mma16816(S3, qh[ks], &kh1[2]);
                mma16816(S0, qh[ks], &kl0[0]); mma16816(S1, qh[ks], &kl0[2]);
                mma16816(S2, qh[ks], &kl1[0]); mma16816(S3, qh[ks], &kl1[2]);
                mma16816(S0, ql[ks], &kh0[0]); mma16816(S1, ql[ks], &kh0[2]);
                mma16816(S2, ql[ks], &kh1[0]); mma16816(S3, ql[ks], &kh1[2]);
            }
        }

        // ---- online softmax (rows lane>>2 and +8; quad reduction) ----
        float mx0 = -1e30f, mx1 = -1e30f;
#pragma unroll
        for (int nt = 0; nt < 8; nt++) {
            mx0 = fmaxf(mx0, fmaxf(S[nt][0], S[nt][1]));
            mx1 = fmaxf(mx1, fmaxf(S[nt][2], S[nt][3]));
        }
        mx0 = fmaxf(mx0, __shfl_xor_sync(0xffffffffu, mx0, 1));
        mx0 = fmaxf(mx0, __shfl_xor_sync(0xffffffffu, mx0, 2));
        mx1 = fmaxf(mx1, __shfl_xor_sync(0xffffffffu, mx1, 1));
        mx1 = fmaxf(mx1, __shfl_xor_sync(0xffffffffu, mx1, 2));
        const float mn0 = fmaxf(m0, mx0), mn1 = fmaxf(m1, mx1);
        const float c0 = __expf(m0 - mn0), c1 = __expf(m1 - mn1);
        m0 = mn0; m1 = mn1;

        float rs0 = 0.f, rs1 = 0.f;
#pragma unroll
        for (int nt = 0; nt < 8; nt++) {
            S[nt][0] = __expf(S[nt][0] - mn0);
            S[nt][1] = __expf(S[nt][1] - mn0);
            S[nt][2] = __expf(S[nt][2] - mn1);
            S[nt][3] = __expf(S[nt][3] - mn1);
            rs0 += S[nt][0] + S[nt][1];
            rs1 += S[nt][2] + S[nt][3];
        }
        rs0 += __shfl_xor_sync(0xffffffffu, rs0, 1);
        rs0 += __shfl_xor_sync(0xffffffffu, rs0, 2);
        rs1 += __shfl_xor_sync(0xffffffffu, rs1, 1);
        rs1 += __shfl_xor_sync(0xffffffffu, rs1, 2);
        sum0 = sum0 * c0 + rs0;
        sum1 = sum1 * c1 + rs1;
#pragma unroll
        for (int nt = 0; nt < 8; nt++) {
            O[nt][0] *= c0; O[nt][1] *= c0;
            O[nt][2] *= c1; O[nt][3] *= c1;
        }

        // ---- ctx += P V (3-pass split; P from regs, V via ldmatrix.trans),
        //      tile-pair interleaved ----
#pragma unroll
        for (int kt = 0; kt < 4; kt++) {
            uint32_t ph[4], pl[4];
            {
                __nv_bfloat162 h;
                h = __floats2bfloat162_rn(S[2 * kt][0], S[2 * kt][1]);
                ph[0] = *(uint32_t*)&h;
                pl[0] = pack2(S[2 * kt][0] - __bfloat162float(h.x),
                              S[2 * kt][1] - __bfloat162float(h.y));
                h = __floats2bfloat162_rn(S[2 * kt][2], S[2 * kt][3]);
                ph[1] = *(uint32_t*)&h;
                pl[1] = pack2(S[2 * kt][2] - __bfloat162float(h.x),
                              S[2 * kt][3] - __bfloat162float(h.y));
                h = __floats2bfloat162_rn(S[2 * kt + 1][0], S[2 * kt + 1][1]);
                ph[2] = *(uint32_t*)&h;
                pl[2] = pack2(S[2 * kt + 1][0] - __bfloat162float(h.x),
                              S[2 * kt + 1][1] - __bfloat162float(h.y));
                h = __floats2bfloat162_rn(S[2 * kt + 1][2], S[2 * kt + 1][3]);
                ph[3] = *(uint32_t*)&h;
                pl[3] = pack2(S[2 * kt + 1][2] - __bfloat162float(h.x),
                              S[2 * kt + 1][3] - __bfloat162float(h.y));
            }
            const int row = kt * 16 + ((lane >> 3) & 1) * 8 + (lane & 7);
#pragma unroll
            for (int up = 0; up < 2; up++) {
                const int c0b = (2 * up) * 32 + (lane >> 4) * 16;
                const uint32_t o0 = sw128((uint32_t)(row * 128 + c0b));
                const uint32_t o1 = sw128((uint32_t)(row * 128 + c0b + 32));
                uint32_t vh0[4], vh1[4], vl0[4], vl1[4];
                ldsm4t(vh0, vbh + o0);
                ldsm4t(vh1, vbh + o1);
                ldsm4t(vl0, vbl + o0);
                ldsm4t(vl1, vbl + o1);
                float* O0 = O[4 * up];     float* O1 = O[4 * up + 1];
                float* O2 = O[4 * up + 2]; float* O3 = O[4 * up + 3];
                mma16816(O0, ph, &vh0[0]); mma16816(O1, ph, &vh0[2]);
                mma16816(O2, ph, &vh1[0]); mma16816(O3, ph, &vh1[2]);
                mma16816(O0, ph, &vl0[0]); mma16816(O1, ph, &vl0[2]);
                mma16816(O2, ph, &vl1[0]); mma16816(O3, ph, &vl1[2]);
                mma16816(O0, pl, &vh0[0]); mma16816(O1, pl, &vh0[2]);
                mma16816(O2, pl, &vh1[0]); mma16816(O3, pl, &vh1[2]);
            }
        }
        __syncthreads();   // all warps done reading stage s before it+2 overwrites
    }

    // ---- epilogue: normalize, write ctx bf16 hi/lo ----
    const float inv0 = 1.f / sum0, inv1 = 1.f / sum1;
    const int r0 = q0 + wr + (lane >> 2);
    const int r1 = r0 + 8;
#pragma unroll
    for (int nt = 0; nt < 8; nt++) {
        const int c = hc + nt * 8 + (lane & 3) * 2;
        const float v0 = O[nt][0] * inv0, v1 = O[nt][1] * inv0;
        const float v2 = O[nt][2] * inv1, v3 = O[nt][3] * inv1;
        __nv_bfloat162 hA = __floats2bfloat162_rn(v0, v1);
        __nv_bfloat162 lA = __floats2bfloat162_rn(v0 - __bfloat162float(hA.x),
                                                  v1 - __bfloat162float(hA.y));
        __nv_bfloat162 hB = __floats2bfloat162_rn(v2, v3);
        __nv_bfloat162 lB = __floats2bfloat162_rn(v2 - __bfloat162float(hB.x),
                                                  v3 - __bfloat162float(hB.y));
        *(__nv_bfloat162*)(Ch + (size_t)r0 * D_MODEL + c) = hA;
        *(__nv_bfloat162*)(Cl + (size_t)r0 * D_MODEL + c) = lA;
        *(__nv_bfloat162*)(Ch + (size_t)r1 * D_MODEL + c) = hB;
        *(__nv_bfloat162*)(Cl + (size_t)r1 * D_MODEL + c) = lB;
    }
}

// ---------------------------------------------------------------------------
// Launch
// ---------------------------------------------------------------------------
extern "C" void kernel_launch(void* const* d_in, const int* in_sizes, int n_in,
                              void* d_out, int out_size) {
    (void)in_sizes; (void)n_in; (void)out_size;
    const float* q  = (const float*)d_in[0];
    const float* k  = (const float*)d_in[1];
    const float* v  = (const float*)d_in[2];
    const float* Wq = (const float*)d_in[3];
    const float* bq = (const float*)d_in[4];
    const float* Wk = (const float*)d_in[5];
    const float* bk = (const float*)d_in[6];
    const float* Wv = (const float*)d_in[7];
    const float* bv = (const float*)d_in[8];
    const float* Wo = (const float*)d_in[9];
    const float* bo = (const float*)d_in[10];
    float* out = (float*)d_out;

    __nv_bfloat16 *Wsh, *Wsl, *Xh, *Xl, *Ph, *Pl;
    cudaGetSymbolAddress((void**)&Wsh, g_Wsh);
    cudaGetSymbolAddress((void**)&Wsl, g_Wsl);
    cudaGetSymbolAddress((void**)&Xh, g_Xh);
    cudaGetSymbolAddress((void**)&Xl, g_Xl);
    cudaGetSymbolAddress((void**)&Ph, g_Ph);
    cudaGetSymbolAddress((void**)&Pl, g_Pl);

    (void)cudaFuncSetAttribute(gemm_tc<true>,  cudaFuncAttributeMaxDynamicSharedMemorySize, TC_SMEM);
    (void)cudaFuncSetAttribute(gemm_tc<false>, cudaFuncAttributeMaxDynamicSharedMemorySize, TC_SMEM);
    (void)cudaFuncSetAttribute(flash_tc, cudaFuncAttributeMaxDynamicSharedMemorySize, FA2_SMEM);

    // 1. Transpose+split all four weights (z = Wq,Wk,Wv,Wo)
    transpose_all<<<dim3(D_MODEL / 32, D_MODEL / 32, 4), dim3(32, 8)>>>(Wq, Wk, Wv, Wo, Wsh, Wsl);
    // 2. Split q,k,v activations
    split_all<<<dim3(SD / 1024, 3), 256>>>(q, k, v, Xh, Xl);
    // 3. Batched Q/K/V projections (z=0: Q with 1/8 scale)
    gemm_tc<true><<<dim3(D_MODEL / TC_BN, SEQ / TC_BM, 3), 256, TC_SMEM>>>(
        Xh, Xl, Wsh, Wsl, bq, bk, bv, nullptr, Ph, Pl, 0.125f);
    // 4. Attention: ctx splits written into Xh/Xl slot 0 (out-proj A operand)
    flash_tc<<<dim3(SEQ / FB_M, NH), 256, FA2_SMEM>>>(
        Ph, Pl, Ph + SD, Pl + SD, Ph + 2 * SD, Pl + 2 * SD, Xh, Xl);
    // 5. Output projection (fp32 out), weight slot 3
    gemm_tc<false><<<dim3(D_MODEL / TC_BN, SEQ / TC_BM, 1), 256, TC_SMEM>>>(
        Xh, Xl, Wsh + 3 * (size_t)DD, Wsl + 3 * (size_t)DD, bo, bo, bo, out, nullptr, nullptr, 1.0f);
}

// round 15
// speedup vs baseline: 1.6011x; 1.6011x over previous
#include <cuda_runtime.h>
#include <cuda_bf16.h>
#include <cstdint>

// Problem constants
#define D_MODEL 768
#define SEQ     4096
#define NH      12
#define DKH     64
#define DD      (D_MODEL * D_MODEL)
#define SD      (SEQ * D_MODEL)

// ---------------------------------------------------------------------------
// Scratch (no allocations allowed -> device globals)
// ---------------------------------------------------------------------------
__device__ __align__(128) __nv_bfloat16 g_Wsh[4 * DD];   // Wq,Wk,Wv,Wo transposed+split hi
__device__ __align__(128) __nv_bfloat16 g_Wsl[4 * DD];   // lo
__device__ __align__(128) __nv_bfloat16 g_Xh[3 * SD];    // q,k,v input splits; later ctx (slot 0)
__device__ __align__(128) __nv_bfloat16 g_Xl[3 * SD];
__device__ __align__(128) __nv_bfloat16 g_Ph[3 * SD];    // projected Q,K,V hi
__device__ __align__(128) __nv_bfloat16 g_Pl[3 * SD];    // lo

// ---------------------------------------------------------------------------
// PTX helpers (plain-sm_103-legal: mma.sync, ldmatrix, cp.async)
// ---------------------------------------------------------------------------
__device__ __forceinline__ uint32_t smem_to_u32(const void* p) {
    uint32_t a;
    asm("{ .reg .u64 t; cvta.to.shared.u64 t, %1; cvt.u32.u64 %0, t; }" : "=r"(a) : "l"(p));
    return a;
}
__device__ __forceinline__ void cp16(uint32_t dst, const void* src) {
    asm volatile("cp.async.cg.shared.global [%0], [%1], 16;" :: "r"(dst), "l"(src) : "memory");
}
#define CP_COMMIT() asm volatile("cp.async.commit_group;" ::: "memory")
#define CP_WAIT(n)  asm volatile("cp.async.wait_group %0;" :: "n"(n) : "memory")

__device__ __forceinline__ void ldsm4(uint32_t* r, uint32_t addr) {
    asm volatile("ldmatrix.sync.aligned.m8n8.x4.shared.b16 {%0,%1,%2,%3}, [%4];"
                 : "=r"(r[0]), "=r"(r[1]), "=r"(r[2]), "=r"(r[3]) : "r"(addr));
}
__device__ __forceinline__ void ldsm4t(uint32_t* r, uint32_t addr) {
    asm volatile("ldmatrix.sync.aligned.m8n8.x4.trans.shared.b16 {%0,%1,%2,%3}, [%4];"
                 : "=r"(r[0]), "=r"(r[1]), "=r"(r[2]), "=r"(r[3]) : "r"(addr));
}
__device__ __forceinline__ void mma16816(float* d, const uint32_t* a, const uint32_t* b) {
    asm volatile("mma.sync.aligned.m16n8k16.row.col.f32.bf16.bf16.f32 "
                 "{%0,%1,%2,%3}, {%4,%5,%6,%7}, {%8,%9}, {%0,%1,%2,%3};"
                 : "+f"(d[0]), "+f"(d[1]), "+f"(d[2]), "+f"(d[3])
                 : "r"(a[0]), "r"(a[1]), "r"(a[2]), "r"(a[3]), "r"(b[0]), "r"(b[1]));
}
__device__ __forceinline__ uint32_t sw128(uint32_t off) { return off ^ ((off >> 3) & 0x70); }
__device__ __forceinline__ uint32_t pack2(float a, float b) {
    __nv_bfloat162 t = __floats2bfloat162_rn(a, b);
    return *(uint32_t*)&t;
}

// ---------------------------------------------------------------------------
// Fused conversion kernels
// ---------------------------------------------------------------------------
__global__ void split_all(const float* __restrict__ q, const float* __restrict__ k,
                          const float* __restrict__ v,
                          __nv_bfloat16* __restrict__ Hi, __nv_bfloat16* __restrict__ Lo) {
    const int z = blockIdx.y;
    const float* A = (z == 0) ? q : (z == 1) ? k : v;
    __nv_bfloat16* hi = Hi + (size_t)z * SD;
    __nv_bfloat16* lo = Lo + (size_t)z * SD;
    const int i = (blockIdx.x * 256 + threadIdx.x) * 4;
    float4 a = *(const float4*)(A + i);
    float vv[4] = {a.x, a.y, a.z, a.w};
#pragma unroll
    for (int j = 0; j < 4; j++) {
        __nv_bfloat16 h = __float2bfloat16(vv[j]);
        hi[i + j] = h;
        lo[i + j] = __float2bfloat16(vv[j] - __bfloat162float(h));
    }
}

// All four W[K,N] row-major -> Wt[N,K] K-major, split into hi/lo
__global__ void transpose_all(const float* __restrict__ W0, const float* __restrict__ W1,
                              const float* __restrict__ W2, const float* __restrict__ W3,
                              __nv_bfloat16* __restrict__ Th, __nv_bfloat16* __restrict__ Tl) {
    const int z = blockIdx.z;
    const float* W = (z == 0) ? W0 : (z == 1) ? W1 : (z == 2) ? W2 : W3;
    __nv_bfloat16* th = Th + (size_t)z * DD;
    __nv_bfloat16* tl = Tl + (size_t)z * DD;
    __shared__ float t[32][33];
    const int bx = blockIdx.x * 32;
    const int by = blockIdx.y * 32;
    const int x = threadIdx.x, y = threadIdx.y;
#pragma unroll
    for (int i = 0; i < 32; i += 8)
        t[y + i][x] = W[(by + y + i) * D_MODEL + bx + x];
    __syncthreads();
#pragma unroll
    for (int i = 0; i < 32; i += 8) {
        const float v = t[x][y + i];
        __nv_bfloat16 h = __float2bfloat16(v);
        const int o = (bx + y + i) * D_MODEL + by + x;
        th[o] = h;
        tl[o] = __float2bfloat16(v - __bfloat162float(h));
    }
}

// ---------------------------------------------------------------------------
// HMMA GEMM (batched over blockIdx.z):
// C_z = (Ah+Al)_z [M,K] @ (Bh+Bl)_z [N,K]^T + bias_z, scale for z==0.
// SPLIT: bf16 hi/lo split output; else fp32.
// ---------------------------------------------------------------------------
#define TC_BM 128
#define TC_BN 128
#define TC_BK 64
#define TC_NKCH (D_MODEL / TC_BK)
#define TC_ITEMS (3 * TC_NKCH)
#define TC_STAGE 32768
#define TC_SMEM  (2 * TC_STAGE)

template <bool SPLIT>
__global__ __launch_bounds__(256)
void gemm_tc(const __nv_bfloat16* __restrict__ Ahb, const __nv_bfloat16* __restrict__ Alb,
             const __nv_bfloat16* __restrict__ Bhb, const __nv_bfloat16* __restrict__ Blb,
             const float* __restrict__ b0, const float* __restrict__ b1,
             const float* __restrict__ b2,
             float* __restrict__ Cf,
             __nv_bfloat16* __restrict__ Chb, __nv_bfloat16* __restrict__ Clb, float scale0) {
    extern __shared__ char smem[];
    const uint32_t sb = smem_to_u32(smem);
    const int tid  = threadIdx.x;
    const int wid  = tid >> 5;
    const int lane = tid & 31;
    const int z    = blockIdx.z;
    const int row0 = blockIdx.y * TC_BM;
    const int col0 = blockIdx.x * TC_BN;
    const int wm = (wid & 3) * 32;
    const int wn = (wid >> 2) * 64;

    const __nv_bfloat16* Ah = Ahb + (size_t)z * SD;
    const __nv_bfloat16* Al = Alb + (size_t)z * SD;
    const __nv_bfloat16* Bh = Bhb + (size_t)z * DD;
    const __nv_bfloat16* Bl = Blb + (size_t)z * DD;
    const float* bias = (z == 0) ? b0 : (z == 1) ? b1 : b2;
    const float scale = (z == 0) ? scale0 : 1.0f;

    float d[2][8][4];
#pragma unroll
    for (int mt = 0; mt < 2; mt++)
#pragma unroll
        for (int nt = 0; nt < 8; nt++)
#pragma unroll
            for (int e = 0; e < 4; e++) d[mt][nt][e] = 0.f;

    auto load_item = [&](int item, int stage) {
        const int pass = item / TC_NKCH;
        const int k0 = (item % TC_NKCH) * TC_BK;
        const __nv_bfloat16* Asrc = (pass == 2) ? Al : Ah;
        const __nv_bfloat16* Bsrc = (pass == 1) ? Bl : Bh;
        const uint32_t base = sb + (uint32_t)stage * TC_STAGE;
#pragma unroll
        for (int i = 0; i < 4; i++) {
            const int v = tid + i * 256;
            const int r = v >> 3;
            const int c = v & 7;
            const uint32_t sw = sw128((uint32_t)(r * 128 + c * 16));
            cp16(base + sw,         Asrc + (size_t)(row0 + r) * D_MODEL + k0 + c * 8);
            cp16(base + 16384 + sw, Bsrc + (size_t)(col0 + r) * D_MODEL + k0 + c * 8);
        }
    };

    load_item(0, 0);
    CP_COMMIT();

    for (int item = 0; item < TC_ITEMS; item++) {
        const int s = item & 1;
        if (item + 1 < TC_ITEMS) {
            load_item(item + 1, s ^ 1);
            CP_COMMIT();
            CP_WAIT(1);
        } else {
            CP_WAIT(0);
        }
        __syncthreads();

        const uint32_t abase = sb + (uint32_t)s * TC_STAGE;
        const uint32_t bbase = abase + 16384;

#pragma unroll
        for (int ks = 0; ks < 4; ks++) {
            uint32_t a[2][4];
#pragma unroll
            for (int mt = 0; mt < 2; mt++) {
                const int r = wm + mt * 16 + (lane & 15);
                const int cb = ks * 32 + ((lane >> 4) << 4);
                ldsm4(a[mt], abase + sw128((uint32_t)(r * 128 + cb)));
            }
#pragma unroll
            for (int t = 0; t < 4; t++) {
                const int nr = wn + t * 16 + ((lane >> 4) << 3) + (lane & 7);
                const int cb = ks * 32 + ((lane >> 3) & 1) * 16;
                uint32_t bb[4];
                ldsm4(bb, bbase + sw128((uint32_t)(nr * 128 + cb)));
#pragma unroll
                for (int mt = 0; mt < 2; mt++) {
                    mma16816(d[mt][t * 2],     a[mt], &bb[0]);
                    mma16816(d[mt][t * 2 + 1], a[mt], &bb[2]);
                }
            }
        }
        __syncthreads();
    }

#pragma unroll
    for (int mt = 0; mt < 2; mt++) {
        const int rA = row0 + wm + mt * 16 + (lane >> 2);
        const int rB = rA + 8;
#pragma unroll
        for (int nt = 0; nt < 8; nt++) {
            const int c = col0 + wn + nt * 8 + (lane & 3) * 2;
            const float bb0 = bias[c], bb1 = bias[c + 1];
            float v0 = (d[mt][nt][0] + bb0) * scale;
            float v1 = (d[mt][nt][1] + bb1) * scale;
            float v2 = (d[mt][nt][2] + bb0) * scale;
            float v3 = (d[mt][nt][3] + bb1) * scale;
            if (!SPLIT) {
                *(float2*)(Cf + (size_t)rA * D_MODEL + c) = make_float2(v0, v1);
                *(float2*)(Cf + (size_t)rB * D_MODEL + c) = make_float2(v2, v3);
            } else {
                __nv_bfloat16* Ch = Chb + (size_t)z * SD;
                __nv_bfloat16* Cl = Clb + (size_t)z * SD;
                __nv_bfloat162 hA = __floats2bfloat162_rn(v0, v1);
                __nv_bfloat162 lA = __floats2bfloat162_rn(v0 - __bfloat162float(hA.x),
                                                          v1 - __bfloat162float(hA.y));
                __nv_bfloat162 hB = __floats2bfloat162_rn(v2, v3);
                __nv_bfloat162 lB = __floats2bfloat162_rn(v2 - __bfloat162float(hB.x),
                                                          v3 - __bfloat162float(hB.y));
                *(__nv_bfloat162*)(Ch + (size_t)rA * D_MODEL + c) = hA;
                *(__nv_bfloat162*)(Cl + (size_t)rA * D_MODEL + c) = lA;
                *(__nv_bfloat162*)(Ch + (size_t)rB * D_MODEL + c) = hB;
                *(__nv_bfloat162*)(Cl + (size_t)rB * D_MODEL + c) = lB;
            }
        }
    }
}

// ---------------------------------------------------------------------------
// HMMA flash attention. CTA = 128 queries x 1 head. 8 warps x m16 rows.
// BN=64 keys/iter, K/V (hi+lo) double-buffered via cp.async.
// S = Qh Kh + Qh Kl + Ql Kh; ctx = Ph Vh + Ph Vl + Pl Vh.
// Round-10 MMA ordering (ptxas schedules it best); minBlocks=2 forces
// <=128 regs so 2 CTAs/SM become resident (reg file was the occ blocker).
// ---------------------------------------------------------------------------
#define FB_M 128
#define FB_N 64
#define F_NITER (SEQ / FB_N)          /* 64 */
#define SQH 0
#define SQL 16384
#define SKV 32768                     /* per-stage: Kh 0 | Kl 8K | Vh 16K | Vl 24K */
#define F_STAGE 32768
#define FA2_SMEM (SKV + 2 * F_STAGE)  /* 98304 */

__global__ __launch_bounds__(256, 2)
void flash_tc(const __nv_bfloat16* __restrict__ Qhg, const __nv_bfloat16* __restrict__ Qlg,
              const __nv_bfloat16* __restrict__ Khg, const __nv_bfloat16* __restrict__ Klg,
              const __nv_bfloat16* __restrict__ Vhg, const __nv_bfloat16* __restrict__ Vlg,
              __nv_bfloat16* __restrict__ Ch, __nv_bfloat16* __restrict__ Cl) {
    extern __shared__ char smem[];
    const uint32_t sb = smem_to_u32(smem);
    const int tid  = threadIdx.x;
    const int wid  = tid >> 5;
    const int lane = tid & 31;
    const int q0 = blockIdx.x * FB_M;
    const int hc = blockIdx.y * DKH;
    const int wr = wid * 16;

    // ---- prologue: Q (hi+lo) + KV stage 0 ----
#pragma unroll
    for (int i = 0; i < 4; i++) {
        const int v = tid + i * 256;
        const int r = v >> 3, c = v & 7;
        const uint32_t sw = sw128((uint32_t)(r * 128 + c * 16));
        cp16(sb + SQH + sw, Qhg + (size_t)(q0 + r) * D_MODEL + hc + c * 8);
        cp16(sb + SQL + sw, Qlg + (size_t)(q0 + r) * D_MODEL + hc + c * 8);
    }
    CP_COMMIT();

    const __nv_bfloat16* kvsrc[4] = {Khg, Klg, Vhg, Vlg};
    auto load_kv = [&](int it, int st) {
        const int kb0 = it * FB_N;
        const uint32_t base = sb + SKV + (uint32_t)st * F_STAGE;
#pragma unroll
        for (int i = 0; i < 8; i++) {
            const int mat = i >> 1;
            const int v = (tid + i * 256) & 511;
            const int r = v >> 3, c = v & 7;
            cp16(base + (uint32_t)mat * 8192u + sw128((uint32_t)(r * 128 + c * 16)),
                 kvsrc[mat] + (size_t)(kb0 + r) * D_MODEL + hc + c * 8);
        }
    };
    load_kv(0, 0);
    CP_COMMIT();
    CP_WAIT(0);
    __syncthreads();

    // ---- resident Q fragments ----
    uint32_t qh[4][4], ql[4][4];
#pragma unroll
    for (int ks = 0; ks < 4; ks++) {
        const int r = wr + (lane & 15);
        const int cb = ks * 32 + ((lane >> 4) << 4);
        const uint32_t off = sw128((uint32_t)(r * 128 + cb));
        ldsm4(qh[ks], sb + SQH + off);
        ldsm4(ql[ks], sb + SQL + off);
    }

    float m0 = -1e30f, m1 = -1e30f, sum0 = 0.f, sum1 = 0.f;
    float O[8][4];
#pragma unroll
    for (int nt = 0; nt < 8; nt++)
#pragma unroll
        for (int e = 0; e < 4; e++) O[nt][e] = 0.f;

#pragma unroll 1
    for (int it = 0; it < F_NITER; it++) {
        const int s = it & 1;
        if (it + 1 < F_NITER) {
            load_kv(it + 1, s ^ 1);
            CP_COMMIT();
            CP_WAIT(1);
        } else {
            CP_WAIT(0);
        }
        __syncthreads();

        const uint32_t kbh = sb + SKV + (uint32_t)s * F_STAGE;
        const uint32_t kbl = kbh + 8192;
        const uint32_t vbh = kbh + 16384;
        const uint32_t vbl = kbh + 24576;

        // ---- S = Q K^T (3-pass split) ----
        float S[8][4];
#pragma unroll
        for (int nt = 0; nt < 8; nt++)
#pragma unroll
            for (int e = 0; e < 4; e++) S[nt][e] = 0.f;

#pragma unroll
        for (int ks = 0; ks < 4; ks++) {
#pragma unroll
            for (int t = 0; t < 4; t++) {
                const int nr = t * 16 + ((lane >> 4) << 3) + (lane & 7);
                const int cb = ks * 32 + ((lane >> 3) & 1) * 16;
                const uint32_t off = sw128((uint32_t)(nr * 128 + cb));
                uint32_t kh4[4], kl4[4];
                ldsm4(kh4, kbh + off);
                ldsm4(kl4, kbl + off);
                mma16816(S[t * 2],     qh[ks], &kh4[0]);
                mma16816(S[t * 2 + 1], qh[ks], &kh4[2]);
                mma16816(S[t * 2],     qh[ks], &kl4[0]);
                mma16816(S[t * 2 + 1], qh[ks], &kl4[2]);
                mma16816(S[t * 2],     ql[ks], &kh4[0]);
                mma16816(S[t * 2 + 1], ql[ks], &kh4[2]);
            }
        }

        // ---- online softmax (rows lane>>2 and +8; quad reduction) ----
        float mx0 = -1e30f, mx1 = -1e30f;
#pragma unroll
        for (int nt = 0; nt < 8; nt++) {
            mx0 = fmaxf(mx0, fmaxf(S[nt][0], S[nt][1]));
            mx1 = fmaxf(mx1, fmaxf(S[nt][2], S[nt][3]));
        }
        mx0 = fmaxf(mx0, __shfl_xor_sync(0xffffffffu, mx0, 1));
        mx0 = fmaxf(mx0, __shfl_xor_sync(0xffffffffu, mx0, 2));
        mx1 = fmaxf(mx1, __shfl_xor_sync(0xffffffffu, mx1, 1));
        mx1 = fmaxf(mx1, __shfl_xor_sync(0xffffffffu, mx1, 2));
        const float mn0 = fmaxf(m0, mx0), mn1 = fmaxf(m1, mx1);
        const float c0 = __expf(m0 - mn0), c1 = __expf(m1 - mn1);
        m0 = mn0; m1 = mn1;

        float rs0 = 0.f, rs1 = 0.f;
#pragma unroll
        for (int nt = 0; nt < 8; nt++) {
            S[nt][0] = __expf(S[nt][0] - mn0);
            S[nt][1] = __expf(S[nt][1] - mn0);
            S[nt][2] = __expf(S[nt][2] - mn1);
            S[nt][3] = __expf(S[nt][3] - mn1);
            rs0 += S[nt][0] + S[nt][1];
            rs1 += S[nt][2] + S[nt][3];
        }
        rs0 += __shfl_xor_sync(0xffffffffu, rs0, 1);
        rs0 += __shfl_xor_sync(0xffffffffu, rs0, 2);
        rs1 += __shfl_xor_sync(0xffffffffu, rs1, 1);
        rs1 += __shfl_xor_sync(0xffffffffu, rs1, 2);
        sum0 = sum0 * c0 + rs0;
        sum1 = sum1 * c1 + rs1;
#pragma unroll
        for (int nt = 0; nt < 8; nt++) {
            O[nt][0] *= c0; O[nt][1] *= c0;
            O[nt][2] *= c1; O[nt][3] *= c1;
        }

        // ---- ctx += P V (3-pass split; P from regs, V via ldmatrix.trans) ----
#pragma unroll
        for (int kt = 0; kt < 4; kt++) {
            uint32_t ph[4], pl[4];
            {
                __nv_bfloat162 h;
                h = __floats2bfloat162_rn(S[2 * kt][0], S[2 * kt][1]);
                ph[0] = *(uint32_t*)&h;
                pl[0] = pack2(S[2 * kt][0] - __bfloat162float(h.x),
                              S[2 * kt][1] - __bfloat162float(h.y));
                h = __floats2bfloat162_rn(S[2 * kt][2], S[2 * kt][3]);
                ph[1] = *(uint32_t*)&h;
                pl[1] = pack2(S[2 * kt][2] - __bfloat162float(h.x),
                              S[2 * kt][3] - __bfloat162float(h.y));
                h = __floats2bfloat162_rn(S[2 * kt + 1][0], S[2 * kt + 1][1]);
                ph[2] = *(uint32_t*)&h;
                pl[2] = pack2(S[2 * kt + 1][0] - __bfloat162float(h.x),
                              S[2 * kt + 1][1] - __bfloat162float(h.y));
                h = __floats2bfloat162_rn(S[2 * kt + 1][2], S[2 * kt + 1][3]);
                ph[3] = *(uint32_t*)&h;
                pl[3] = pack2(S[2 * kt + 1][2] - __bfloat162float(h.x),
                              S[2 * kt + 1][3] - __bfloat162float(h.y));
            }
#pragma unroll
            for (int u = 0; u < 4; u++) {
                const int row = kt * 16 + ((lane >> 3) & 1) * 8 + (lane & 7);
                const int col = u * 32 + (lane >> 4) * 16;
                const uint32_t off = sw128((uint32_t)(row * 128 + col));
                uint32_t vh4[4], vl4[4];
                ldsm4t(vh4, vbh + off);
                ldsm4t(vl4, vbl + off);
                mma16816(O[u * 2],     ph, &vh4[0]);
                mma16816(O[u * 2 + 1], ph, &vh4[2]);
                mma16816(O[u * 2],     ph, &vl4[0]);
                mma16816(O[u * 2 + 1], ph, &vl4[2]);
                mma16816(O[u * 2],     pl, &vh4[0]);
                mma16816(O[u * 2 + 1], pl, &vh4[2]);
            }
        }
        __syncthreads();   // all warps done reading stage s before it+2 overwrites
    }

    // ---- epilogue: normalize, write ctx bf16 hi/lo ----
    const float inv0 = 1.f / sum0, inv1 = 1.f / sum1;
    const int r0 = q0 + wr + (lane >> 2);
    const int r1 = r0 + 8;
#pragma unroll
    for (int nt = 0; nt < 8; nt++) {
        const int c = hc + nt * 8 + (lane & 3) * 2;
        const float v0 = O[nt][0] * inv0, v1 = O[nt][1] * inv0;
        const float v2 = O[nt][2] * inv1, v3 = O[nt][3] * inv1;
        __nv_bfloat162 hA = __floats2bfloat162_rn(v0, v1);
        __nv_bfloat162 lA = __floats2bfloat162_rn(v0 - __bfloat162float(hA.x),
                                                  v1 - __bfloat162float(hA.y));
        __nv_bfloat162 hB = __floats2bfloat162_rn(v2, v3);
        __nv_bfloat162 lB = __floats2bfloat162_rn(v2 - __bfloat162float(hB.x),
                                                  v3 - __bfloat162float(hB.y));
        *(__nv_bfloat162*)(Ch + (size_t)r0 * D_MODEL + c) = hA;
        *(__nv_bfloat162*)(Cl + (size_t)r0 * D_MODEL + c) = lA;
        *(__nv_bfloat162*)(Ch + (size_t)r1 * D_MODEL + c) = hB;
        *(__nv_bfloat162*)(Cl + (size_t)r1 * D_MODEL + c) = lB;
    }
}

// ---------------------------------------------------------------------------
// Launch
// ---------------------------------------------------------------------------
extern "C" void kernel_launch(void* const* d_in, const int* in_sizes, int n_in,
                              void* d_out, int out_size) {
    (void)in_sizes; (void)n_in; (void)out_size;
    const float* q  = (const float*)d_in[0];
    const float* k  = (const float*)d_in[1];
    const float* v  = (const float*)d_in[2];
    const float* Wq = (const float*)d_in[3];
    const float* bq = (const float*)d_in[4];
    const float* Wk = (const float*)d_in[5];
    const float* bk = (const float*)d_in[6];
    const float* Wv = (const float*)d_in[7];
    const float* bv = (const float*)d_in[8];
    const float* Wo = (const float*)d_in[9];
    const float* bo = (const float*)d_in[10];
    float* out = (float*)d_out;

    __nv_bfloat16 *Wsh, *Wsl, *Xh, *Xl, *Ph, *Pl;
    cudaGetSymbolAddress((void**)&Wsh, g_Wsh);
    cudaGetSymbolAddress((void**)&Wsl, g_Wsl);
    cudaGetSymbolAddress((void**)&Xh, g_Xh);
    cudaGetSymbolAddress((void**)&Xl, g_Xl);
    cudaGetSymbolAddress((void**)&Ph, g_Ph);
    cudaGetSymbolAddress((void**)&Pl, g_Pl);

    (void)cudaFuncSetAttribute(gemm_tc<true>,  cudaFuncAttributeMaxDynamicSharedMemorySize, TC_SMEM);
    (void)cudaFuncSetAttribute(gemm_tc<false>, cudaFuncAttributeMaxDynamicSharedMemorySize, TC_SMEM);
    (void)cudaFuncSetAttribute(flash_tc, cudaFuncAttributeMaxDynamicSharedMemorySize, FA2_SMEM);

    // 1. Transpose+split all four weights (z = Wq,Wk,Wv,Wo)
    transpose_all<<<dim3(D_MODEL / 32, D_MODEL / 32, 4), dim3(32, 8)>>>(Wq, Wk, Wv, Wo, Wsh, Wsl);
    // 2. Split q,k,v activations
    split_all<<<dim3(SD / 1024, 3), 256>>>(q, k, v, Xh, Xl);
    // 3. Batched Q/K/V projections (z=0: Q with 1/8 scale)
    gemm_tc<true><<<dim3(D_MODEL / TC_BN, SEQ / TC_BM, 3), 256, TC_SMEM>>>(
        Xh, Xl, Wsh, Wsl, bq, bk, bv, nullptr, Ph, Pl, 0.125f);
    // 4. Attention: ctx splits written into Xh/Xl slot 0 (out-proj A operand)
    flash_tc<<<dim3(SEQ / FB_M, NH), 256, FA2_SMEM>>>(
        Ph, Pl, Ph + SD, Pl + SD, Ph + 2 * SD, Pl + 2 * SD, Xh, Xl);
    // 5. Output projection (fp32 out), weight slot 3
    gemm_tc<false><<<dim3(D_MODEL / TC_BN, SEQ / TC_BM, 1), 256, TC_SMEM>>>(
        Xh, Xl, Wsh + 3 * (size_t)DD, Wsl + 3 * (size_t)DD, bo, bo, bo, out, nullptr, nullptr, 1.0f);
}